// round 12
// baseline (speedup 1.0000x reference)
#include <cuda_runtime.h>
#include <cuda_bf16.h>
#include <cstdint>

#define N_NODES 50000
#define CH      256
#define N_EDGES 800000
#define N_CSR   (N_EDGES + N_NODES)
#define NSCAN   196          // ceil(50000/256)

// ---------------- scratch (device globals) ------------------------------------
__device__ float g_xw [N_NODES * CH];    // x @ conv_w fp32 (51.2 MB)
__device__ __nv_bfloat16 g_xhi[N_NODES * CH];
__device__ __nv_bfloat16 g_xlo[N_NODES * CH];
__device__ __nv_bfloat16 g_whi[CH * CH]; // W^T hi, [n][k]
__device__ __nv_bfloat16 g_wlo[CH * CH];
__device__ float g_dinv[N_NODES];
__device__ int   g_sdeg[N_NODES];
__device__ int   g_cnt [N_NODES];
__device__ int   g_rowptr[N_NODES];
__device__ int   g_cursor[N_NODES];
__device__ int   g_bsum[NSCAN];
__device__ int2  g_csr[N_CSR];           // {src, coef-as-int}; includes self edges
__device__ float g_s[CH];

__device__ __forceinline__ uint32_t packbf(float a, float b) {
    __nv_bfloat162 t = __floats2bfloat162_rn(a, b);
    return *(uint32_t*)&t;
}

// ---------------- prep: init counters + split/transpose W -----------------------
__global__ void k_prep(const float* __restrict__ W) {
    int i = blockIdx.x * blockDim.x + threadIdx.x;   // 0..65535
    if (i < N_NODES) { g_sdeg[i] = 1; g_cnt[i] = 1; }  // cnt=1: self edge slot
    if (i < CH)      g_s[i] = 0.0f;
    int k = i >> 8, n = i & 255;
    float f = W[i];                                   // W[k][n]
    __nv_bfloat16 h = __float2bfloat16_rn(f);
    g_whi[n * CH + k] = h;
    g_wlo[n * CH + k] = __float2bfloat16_rn(f - __bfloat162float(h));
}

// ---------------- X bf16 hi/lo split --------------------------------------------
__global__ void k_splitX(const float* __restrict__ X) {
    int idx = blockIdx.x * blockDim.x + threadIdx.x;  // 0..3,199,999 (float4)
    float4 v = ((const float4*)X)[idx];
    uint2 hi, lo;
    hi.x = packbf(v.x, v.y);
    hi.y = packbf(v.z, v.w);
    lo.x = packbf(v.x - __bfloat162float(__float2bfloat16_rn(v.x)),
                  v.y - __bfloat162float(__float2bfloat16_rn(v.y)));
    lo.y = packbf(v.z - __bfloat162float(__float2bfloat16_rn(v.z)),
                  v.w - __bfloat162float(__float2bfloat16_rn(v.w)));
    ((uint2*)g_xhi)[idx] = hi;
    ((uint2*)g_xlo)[idx] = lo;
}

// ---------------- degree histograms ----------------------------------------------
__global__ void k_count(const int* __restrict__ src, const int* __restrict__ dst) {
    int e = blockIdx.x * blockDim.x + threadIdx.x;
    if (e < N_EDGES) {
        atomicAdd(&g_sdeg[src[e]], 1);
        atomicAdd(&g_cnt[dst[e]], 1);
    }
}

// ---------------- 3-kernel exclusive scan over g_cnt ----------------------------
__global__ void k_scan1() {
    __shared__ int sh[256];
    int t = threadIdx.x, i = blockIdx.x * 256 + t;
    int v = (i < N_NODES) ? g_cnt[i] : 0;
    sh[t] = v; __syncthreads();
    #pragma unroll
    for (int off = 1; off < 256; off <<= 1) {
        int add = (t >= off) ? sh[t - off] : 0;
        __syncthreads();
        sh[t] += add;
        __syncthreads();
    }
    if (i < N_NODES) g_rowptr[i] = sh[t] - v;
    if (t == 255) g_bsum[blockIdx.x] = sh[255];
}

__global__ void k_scan2() {
    __shared__ int sh[256];
    int t = threadIdx.x;
    int v = (t < NSCAN) ? g_bsum[t] : 0;
    sh[t] = v; __syncthreads();
    #pragma unroll
    for (int off = 1; off < 256; off <<= 1) {
        int add = (t >= off) ? sh[t - off] : 0;
        __syncthreads();
        sh[t] += add;
        __syncthreads();
    }
    if (t < NSCAN) g_bsum[t] = sh[t] - v;
}

// scan finalize + dinv + write self edge at rowptr[i]
__global__ void k_scan3d() {
    int i = blockIdx.x * blockDim.x + threadIdx.x;
    if (i < N_NODES) {
        int r = g_rowptr[i] + g_bsum[i >> 8];
        g_rowptr[i] = r;
        g_cursor[i] = r + 1;                         // slot r = self edge
        int deg = g_sdeg[i];
        g_dinv[i] = rsqrtf((float)deg);
        g_csr[r] = make_int2(i, __float_as_int(1.0f / (float)deg));
    }
}

// ---------------- CSR fill (packed int2 metadata) --------------------------------
__global__ void k_fill(const int* __restrict__ src, const int* __restrict__ dst) {
    int e = blockIdx.x * blockDim.x + threadIdx.x;
    if (e < N_EDGES) {
        int s = src[e], d = dst[e];
        int pos = atomicAdd(&g_cursor[d], 1);
        float cf = g_dinv[s] * g_dinv[d];
        g_csr[pos] = make_int2(s, __float_as_int(cf));
    }
}

// =================================================================================
// Split-bf16 GEMM: D = Xhi*Whi + Xhi*Wlo + Xlo*Whi.
// 4-stage cp.async pipeline (K chunk 16), ldmatrix, 2 CTAs/SM.
// CTA 128x128, 8 warps 4(M)x2(N).  Stage = A hi/lo + B hi/lo, rows padded to 48B.
// =================================================================================
#define TB_M 128
#define TB_N 128
#define ROWB 48            // bytes per SMEM row (16 bf16 + pad) -> conflict-free LDSM
#define OFF_AHI 0
#define OFF_ALO 6144
#define OFF_BHI 12288
#define OFF_BLO 18432
#define STAGE_BYTES 24576
#define NSTAGE 4
#define GEMM_SMEM (NSTAGE * STAGE_BYTES)   // 98304 per CTA

__device__ __forceinline__ uint32_t smem_u32(const void* p) {
    uint32_t a;
    asm("{ .reg .u64 t; cvta.to.shared.u64 t, %1; cvt.u32.u64 %0, t; }"
        : "=r"(a) : "l"(p));
    return a;
}
#define CP16(dst, src) \
    asm volatile("cp.async.cg.shared.global [%0], [%1], 16;" :: "r"(dst), "l"(src))

__device__ __forceinline__ void ldsm4(uint32_t* r, uint32_t addr) {
    asm volatile("ldmatrix.sync.aligned.m8n8.x4.shared.b16 {%0,%1,%2,%3}, [%4];"
        : "=r"(r[0]), "=r"(r[1]), "=r"(r[2]), "=r"(r[3]) : "r"(addr));
}

__device__ __forceinline__ void mma16816(float* c, const uint32_t* a, const uint32_t* b) {
    asm volatile(
        "mma.sync.aligned.m16n8k16.row.col.f32.bf16.bf16.f32 "
        "{%0,%1,%2,%3}, {%4,%5,%6,%7}, {%8,%9}, {%0,%1,%2,%3};"
        : "+f"(c[0]), "+f"(c[1]), "+f"(c[2]), "+f"(c[3])
        : "r"(a[0]), "r"(a[1]), "r"(a[2]), "r"(a[3]), "r"(b[0]), "r"(b[1]));
}

__global__ void __launch_bounds__(256, 2) k_gemm_mma() {
    extern __shared__ char dsm[];
    const uint32_t sb = smem_u32(dsm);
    const int tid  = threadIdx.x;
    const int wid  = tid >> 5;
    const int lane = tid & 31;
    const int wm   = wid >> 1;
    const int wn   = wid & 1;
    const int bm   = blockIdx.y * TB_M;          // M slow
    const int n0   = blockIdx.x * TB_N;          // N fast -> X L2 reuse

    const int qr = lane >> 2;
    const int qc = lane & 3;

    const uint32_t a_l = (uint32_t)((wm * 32 + (lane & 15)) * ROWB + ((lane & 16) ? 16 : 0));
    const uint32_t b_l = (uint32_t)((wn * 64 + (lane & 7) + ((lane & 16) ? 8 : 0)) * ROWB
                                    + ((lane & 8) ? 16 : 0));

    const int crow = tid >> 1;                   // 0..127 (cp.async row)
    const int cseg = tid & 1;                    // 16B segment within 32B row

    float acc[2][8][4];
    #pragma unroll
    for (int mi = 0; mi < 2; mi++)
        #pragma unroll
        for (int ni = 0; ni < 8; ni++)
            #pragma unroll
            for (int j = 0; j < 4; j++) acc[mi][ni][j] = 0.f;

    // issue one chunk (16 k-cols) into a stage: 4 CP16 per thread
    #define ISSUE(kc) { \
        const int k0_ = (kc) * 16; \
        const uint32_t base_ = sb + ((kc) & 3) * STAGE_BYTES; \
        int gr = bm + crow; if (gr > N_NODES - 1) gr = N_NODES - 1; \
        CP16(base_ + OFF_AHI + crow * ROWB + cseg * 16, \
             (const char*)(g_xhi + gr * CH + k0_ + cseg * 8)); \
        CP16(base_ + OFF_ALO + crow * ROWB + cseg * 16, \
             (const char*)(g_xlo + gr * CH + k0_ + cseg * 8)); \
        CP16(base_ + OFF_BHI + crow * ROWB + cseg * 16, \
             (const char*)(g_whi + (n0 + crow) * CH + k0_ + cseg * 8)); \
        CP16(base_ + OFF_BLO + crow * ROWB + cseg * 16, \
             (const char*)(g_wlo + (n0 + crow) * CH + k0_ + cseg * 8)); \
        asm volatile("cp.async.commit_group;"); }

    ISSUE(0) ISSUE(1) ISSUE(2)

    for (int kc = 0; kc < 16; kc++) {
        // wait until chunk kc's group is retired
        if (kc <= 13)      asm volatile("cp.async.wait_group 2;");
        else if (kc == 14) asm volatile("cp.async.wait_group 1;");
        else               asm volatile("cp.async.wait_group 0;");
        __syncthreads();           // chunk kc visible to all; all done with kc-1

        if (kc <= 12) ISSUE(kc + 3)   // overwrites stage of chunk kc-1 (safe post-sync)

        const uint32_t base = sb + (kc & 3) * STAGE_BYTES;
        const uint32_t aHi = base + OFF_AHI + a_l;
        const uint32_t aLo = base + OFF_ALO + a_l;
        const uint32_t bHi = base + OFF_BHI + b_l;
        const uint32_t bLo = base + OFF_BLO + b_l;

        uint32_t ah[2][4], al[2][4], bh[8][2], bl[8][2];
        #pragma unroll
        for (int mi = 0; mi < 2; mi++) {
            ldsm4(ah[mi], aHi + mi * (16 * ROWB));
            ldsm4(al[mi], aLo + mi * (16 * ROWB));
        }
        #pragma unroll
        for (int p = 0; p < 4; p++) {
            ldsm4(&bh[2 * p][0], bHi + p * (16 * ROWB));
            ldsm4(&bl[2 * p][0], bLo + p * (16 * ROWB));
        }
        #pragma unroll
        for (int mi = 0; mi < 2; mi++)
            #pragma unroll
            for (int ni = 0; ni < 8; ni++)
                mma16816(acc[mi][ni], ah[mi], bh[ni]);
        #pragma unroll
        for (int mi = 0; mi < 2; mi++)
            #pragma unroll
            for (int ni = 0; ni < 8; ni++)
                mma16816(acc[mi][ni], ah[mi], bl[ni]);
        #pragma unroll
        for (int mi = 0; mi < 2; mi++)
            #pragma unroll
            for (int ni = 0; ni < 8; ni++)
                mma16816(acc[mi][ni], al[mi], bh[ni]);
    }

    // ---- epilogue: fp32 stores (cols 2qc, 2qc+1) ----
    #pragma unroll
    for (int mi = 0; mi < 2; mi++) {
        int r0 = bm + wm * 32 + mi * 16 + qr;
        #pragma unroll
        for (int ni = 0; ni < 8; ni++) {
            int cg = n0 + wn * 64 + ni * 8 + qc * 2;
            if (r0 < N_NODES)
                *(float2*)&g_xw[r0 * CH + cg] = make_float2(acc[mi][ni][0], acc[mi][ni][1]);
            if (r0 + 8 < N_NODES)
                *(float2*)&g_xw[(r0 + 8) * CH + cg] = make_float2(acc[mi][ni][2], acc[mi][ni][3]);
        }
    }
}

// ---------------- fused gather + relu + node-sum (self edge in CSR) --------------
#define GATHER_BLOCKS 1184
__global__ void __launch_bounds__(256) k_gather(const float* __restrict__ conv_b) {
    __shared__ float sacc[CH];
    const int tid  = threadIdx.x;
    const int lane = tid & 31;
    const int warp = (blockIdx.x * blockDim.x + tid) >> 5;
    const int nwarps = (GATHER_BLOCKS * 256) >> 5;
    const int c = lane << 3;

    sacc[tid] = 0.f;
    __syncthreads();

    const float4 b0 = *(const float4*)&conv_b[c];
    const float4 b1 = *(const float4*)&conv_b[c + 4];
    float hs[8] = {0.f,0.f,0.f,0.f,0.f,0.f,0.f,0.f};

    // prefetch first node's metadata
    int beg = 0, cnt = 0;
    if (warp < N_NODES) { beg = g_rowptr[warp]; cnt = g_cnt[warp]; }

    for (int n = warp; n < N_NODES; n += nwarps) {
        // prefetch next node's rowptr/cnt
        int nn = n + nwarps, nbeg = 0, ncnt = 0;
        if (nn < N_NODES) { nbeg = g_rowptr[nn]; ncnt = g_cnt[nn]; }

        float a[8] = {0.f,0.f,0.f,0.f,0.f,0.f,0.f,0.f};
        const int2* ec = g_csr + beg;
        const int nb = cnt >> 3;

        #define GSTEP(e) { \
            const float* p = &g_xw[(e).x * CH + c]; \
            float4 v0 = *(const float4*)p; \
            float4 v1 = *(const float4*)(p + 4); \
            float cf = __int_as_float((e).y); \
            a[0] += cf * v0.x; a[1] += cf * v0.y; \
            a[2] += cf * v0.z; a[3] += cf * v0.w; \
            a[4] += cf * v1.x; a[5] += cf * v1.y; \
            a[6] += cf * v1.z; a[7] += cf * v1.w; }

        if (nb > 0) {
            int2 m0 = ec[0], m1 = ec[1], m2 = ec[2], m3 = ec[3],
                 m4 = ec[4], m5 = ec[5], m6 = ec[6], m7 = ec[7];
            for (int bi = 0; bi < nb; bi++) {
                int2 c0 = m0, c1 = m1, c2 = m2, c3 = m3,
                     c4 = m4, c5 = m5, c6 = m6, c7 = m7;
                if (bi + 1 < nb) {
                    const int2* nx = ec + (bi + 1) * 8;
                    m0 = nx[0]; m1 = nx[1]; m2 = nx[2]; m3 = nx[3];
                    m4 = nx[4]; m5 = nx[5]; m6 = nx[6]; m7 = nx[7];
                }
                GSTEP(c0) GSTEP(c1) GSTEP(c2) GSTEP(c3)
                GSTEP(c4) GSTEP(c5) GSTEP(c6) GSTEP(c7)
            }
        }
        // batched remainder: all metadata loads in flight before gathers
        {
            int base = nb << 3;
            int rem  = cnt - base;
            int2 rr[7];
            #pragma unroll
            for (int j = 0; j < 7; j++) if (j < rem) rr[j] = ec[base + j];
            #pragma unroll
            for (int j = 0; j < 7; j++) if (j < rem) GSTEP(rr[j])
        }
        #undef GSTEP
        hs[0] += fmaxf(a[0] + b0.x, 0.f);
        hs[1] += fmaxf(a[1] + b0.y, 0.f);
        hs[2] += fmaxf(a[2] + b0.z, 0.f);
        hs[3] += fmaxf(a[3] + b0.w, 0.f);
        hs[4] += fmaxf(a[4] + b1.x, 0.f);
        hs[5] += fmaxf(a[5] + b1.y, 0.f);
        hs[6] += fmaxf(a[6] + b1.z, 0.f);
        hs[7] += fmaxf(a[7] + b1.w, 0.f);

        beg = nbeg; cnt = ncnt;
    }
    #pragma unroll
    for (int i = 0; i < 8; i++) atomicAdd(&sacc[c + i], hs[i]);
    __syncthreads();
    atomicAdd(&g_s[tid], sacc[tid]);
}

// ---------------- 4 tanh GEMVs -----------------------------------------------------
__global__ void k_gemv(const float* __restrict__ fc1w, const float* __restrict__ fc1b,
                       const float* __restrict__ fc2w, const float* __restrict__ fc2b,
                       const float* __restrict__ fc3w, const float* __restrict__ fc3b,
                       const float* __restrict__ fc4w, const float* __restrict__ fc4b,
                       float* __restrict__ out) {
    __shared__ float ss[CH];
    const int t = threadIdx.x;
    if (t < CH) ss[t] = g_s[t];
    __syncthreads();

    const float* w; const float* bb; int row;
    if (t < 256)      { w = fc1w; bb = fc1b; row = t; }
    else if (t < 512) { w = fc2w; bb = fc2b; row = t - 256; }
    else if (t < 640) { w = fc3w; bb = fc3b; row = t - 512; }
    else              { w = fc4w; bb = fc4b; row = t - 640; }

    float acc = bb[row];
    const float4* wr = (const float4*)(w + row * CH);
    #pragma unroll
    for (int k = 0; k < CH / 4; k++) {
        float4 wv = wr[k];
        acc += ss[4 * k + 0] * wv.x + ss[4 * k + 1] * wv.y +
               ss[4 * k + 2] * wv.z + ss[4 * k + 3] * wv.w;
    }
    out[t] = tanhf(acc);
}

// ---------------- launch -------------------------------------------------------------
extern "C" void kernel_launch(void* const* d_in, const int* in_sizes, int n_in,
                              void* d_out, int out_size) {
    const float* x      = (const float*)d_in[0];
    const int*   ei     = (const int*)  d_in[1];
    const float* conv_w = (const float*)d_in[2];
    const float* conv_b = (const float*)d_in[3];
    const float* fc1w   = (const float*)d_in[4];
    const float* fc1b   = (const float*)d_in[5];
    const float* fc2w   = (const float*)d_in[6];
    const float* fc2b   = (const float*)d_in[7];
    const float* fc3w   = (const float*)d_in[8];
    const float* fc3b   = (const float*)d_in[9];
    const float* fc4w   = (const float*)d_in[10];
    const float* fc4b   = (const float*)d_in[11];
    float* out = (float*)d_out;

    const int* src = ei;
    const int* dst = ei + N_EDGES;

    static cudaStream_t sB = 0;
    static cudaEvent_t ePrep = 0, eGemm = 0;
    static bool inited = false;
    if (!inited) {
        cudaFuncSetAttribute(k_gemm_mma, cudaFuncAttributeMaxDynamicSharedMemorySize,
                             GEMM_SMEM);
        cudaStreamCreateWithFlags(&sB, cudaStreamNonBlocking);
        cudaEventCreateWithFlags(&ePrep, cudaEventDisableTiming);
        cudaEventCreateWithFlags(&eGemm, cudaEventDisableTiming);
        inited = true;
    }

    // sB: splitX (needs only X) runs concurrently with prep+count on main
    k_splitX<<<N_NODES * CH / 4 / 256, 256, 0, sB>>>(x);       // 1
    k_prep<<<256, 256>>>(conv_w);                              // 2 (main)
    cudaEventRecord(ePrep, 0);
    k_count<<<(N_EDGES + 255) / 256, 256>>>(src, dst);         // 3 (main)

    // sB: GEMM after splitX (stream order) and prep (event)
    cudaStreamWaitEvent(sB, ePrep, 0);
    dim3 gg(CH / TB_N, (N_NODES + TB_M - 1) / TB_M);
    k_gemm_mma<<<gg, 256, GEMM_SMEM, sB>>>();                  // 4 <- profiled
    cudaEventRecord(eGemm, sB);

    // main: CSR chain (overlaps GEMM)
    k_scan1<<<NSCAN, 256>>>();                                 // 5
    k_scan2<<<1, 256>>>();                                     // 6
    k_scan3d<<<NSCAN, 256>>>();                                // 7
    k_fill<<<(N_EDGES + 255) / 256, 256>>>(src, dst);          // 8

    // join: gather needs CSR (stream order) + GEMM (event)
    cudaStreamWaitEvent(0, eGemm, 0);
    k_gather<<<GATHER_BLOCKS, 256>>>(conv_b);                  // 9
    k_gemv<<<1, 768>>>(fc1w, fc1b, fc2w, fc2b, fc3w, fc3b, fc4w, fc4b, out); // 10
}

// round 13
// speedup vs baseline: 1.2023x; 1.2023x over previous
#include <cuda_runtime.h>
#include <cuda_bf16.h>
#include <cuda_fp16.h>
#include <cstdint>

#define N_NODES 50000
#define CH      256
#define N_EDGES 800000
#define N_CSR   (N_EDGES + N_NODES)
#define NSCAN   196          // ceil(50000/256)

// ---------------- scratch (device globals) ------------------------------------
__device__ __half g_xwh[N_NODES * CH];   // x @ conv_w, fp16 (25.6 MB, L2-resident)
__device__ __nv_bfloat16 g_xhi[N_NODES * CH];
__device__ __nv_bfloat16 g_xlo[N_NODES * CH];
__device__ __nv_bfloat16 g_whi[CH * CH]; // W^T hi, [n][k]
__device__ __nv_bfloat16 g_wlo[CH * CH];
__device__ float g_dinv[N_NODES];
__device__ int   g_sdeg[N_NODES];
__device__ int   g_cnt [N_NODES];
__device__ int   g_rowptr[N_NODES];
__device__ int   g_cursor[N_NODES];
__device__ int   g_bsum[NSCAN];
__device__ int2  g_csr[N_CSR];           // {src, coef-as-int}; includes self edges
__device__ float g_s[CH];

__device__ __forceinline__ uint32_t packbf(float a, float b) {
    __nv_bfloat162 t = __floats2bfloat162_rn(a, b);
    return *(uint32_t*)&t;
}

// ---------------- prep: init counters + split/transpose W -----------------------
__global__ void k_prep(const float* __restrict__ W) {
    int i = blockIdx.x * blockDim.x + threadIdx.x;   // 0..65535
    if (i < N_NODES) { g_sdeg[i] = 1; g_cnt[i] = 1; }  // cnt=1: self edge slot
    if (i < CH)      g_s[i] = 0.0f;
    int k = i >> 8, n = i & 255;
    float f = W[i];                                   // W[k][n]
    __nv_bfloat16 h = __float2bfloat16_rn(f);
    g_whi[n * CH + k] = h;
    g_wlo[n * CH + k] = __float2bfloat16_rn(f - __bfloat162float(h));
}

// ---------------- X bf16 hi/lo split --------------------------------------------
__global__ void k_splitX(const float* __restrict__ X) {
    int idx = blockIdx.x * blockDim.x + threadIdx.x;  // 0..3,199,999 (float4)
    float4 v = ((const float4*)X)[idx];
    uint2 hi, lo;
    hi.x = packbf(v.x, v.y);
    hi.y = packbf(v.z, v.w);
    lo.x = packbf(v.x - __bfloat162float(__float2bfloat16_rn(v.x)),
                  v.y - __bfloat162float(__float2bfloat16_rn(v.y)));
    lo.y = packbf(v.z - __bfloat162float(__float2bfloat16_rn(v.z)),
                  v.w - __bfloat162float(__float2bfloat16_rn(v.w)));
    ((uint2*)g_xhi)[idx] = hi;
    ((uint2*)g_xlo)[idx] = lo;
}

// ---------------- degree histograms ----------------------------------------------
__global__ void k_count(const int* __restrict__ src, const int* __restrict__ dst) {
    int e = blockIdx.x * blockDim.x + threadIdx.x;
    if (e < N_EDGES) {
        atomicAdd(&g_sdeg[src[e]], 1);
        atomicAdd(&g_cnt[dst[e]], 1);
    }
}

// ---------------- 3-kernel exclusive scan over g_cnt ----------------------------
__global__ void k_scan1() {
    __shared__ int sh[256];
    int t = threadIdx.x, i = blockIdx.x * 256 + t;
    int v = (i < N_NODES) ? g_cnt[i] : 0;
    sh[t] = v; __syncthreads();
    #pragma unroll
    for (int off = 1; off < 256; off <<= 1) {
        int add = (t >= off) ? sh[t - off] : 0;
        __syncthreads();
        sh[t] += add;
        __syncthreads();
    }
    if (i < N_NODES) g_rowptr[i] = sh[t] - v;
    if (t == 255) g_bsum[blockIdx.x] = sh[255];
}

__global__ void k_scan2() {
    __shared__ int sh[256];
    int t = threadIdx.x;
    int v = (t < NSCAN) ? g_bsum[t] : 0;
    sh[t] = v; __syncthreads();
    #pragma unroll
    for (int off = 1; off < 256; off <<= 1) {
        int add = (t >= off) ? sh[t - off] : 0;
        __syncthreads();
        sh[t] += add;
        __syncthreads();
    }
    if (t < NSCAN) g_bsum[t] = sh[t] - v;
}

// scan finalize + dinv + write self edge at rowptr[i]
__global__ void k_scan3d() {
    int i = blockIdx.x * blockDim.x + threadIdx.x;
    if (i < N_NODES) {
        int r = g_rowptr[i] + g_bsum[i >> 8];
        g_rowptr[i] = r;
        g_cursor[i] = r + 1;                         // slot r = self edge
        int deg = g_sdeg[i];
        g_dinv[i] = rsqrtf((float)deg);
        g_csr[r] = make_int2(i, __float_as_int(1.0f / (float)deg));
    }
}

// ---------------- CSR fill (packed int2 metadata) --------------------------------
__global__ void k_fill(const int* __restrict__ src, const int* __restrict__ dst) {
    int e = blockIdx.x * blockDim.x + threadIdx.x;
    if (e < N_EDGES) {
        int s = src[e], d = dst[e];
        int pos = atomicAdd(&g_cursor[d], 1);
        float cf = g_dinv[s] * g_dinv[d];
        g_csr[pos] = make_int2(s, __float_as_int(cf));
    }
}

// =================================================================================
// Split-bf16 GEMM: D = Xhi*Whi + Xhi*Wlo + Xlo*Whi, cp.async 2-stage, ldmatrix,
// 2 CTAs/SM. CTA 128x128, 8 warps 4(M)x2(N), K chunk 32. Epilogue stores fp16.
// =================================================================================
#define TB_M 128
#define TB_N 128
#define ROWB 80            // bytes per SMEM row (40 bf16) -> conflict-free LDSM
#define OFF_AHI 0
#define OFF_ALO 10240
#define OFF_BHI 20480
#define OFF_BLO 30720
#define STAGE_BYTES 40960
#define GEMM_SMEM (2 * STAGE_BYTES)

__device__ __forceinline__ uint32_t smem_u32(const void* p) {
    uint32_t a;
    asm("{ .reg .u64 t; cvta.to.shared.u64 t, %1; cvt.u32.u64 %0, t; }"
        : "=r"(a) : "l"(p));
    return a;
}
#define CP16(dst, src) \
    asm volatile("cp.async.cg.shared.global [%0], [%1], 16;" :: "r"(dst), "l"(src))

__device__ __forceinline__ void ldsm4(uint32_t* r, uint32_t addr) {
    asm volatile("ldmatrix.sync.aligned.m8n8.x4.shared.b16 {%0,%1,%2,%3}, [%4];"
        : "=r"(r[0]), "=r"(r[1]), "=r"(r[2]), "=r"(r[3]) : "r"(addr));
}

__device__ __forceinline__ void mma16816(float* c, const uint32_t* a, const uint32_t* b) {
    asm volatile(
        "mma.sync.aligned.m16n8k16.row.col.f32.bf16.bf16.f32 "
        "{%0,%1,%2,%3}, {%4,%5,%6,%7}, {%8,%9}, {%0,%1,%2,%3};"
        : "+f"(c[0]), "+f"(c[1]), "+f"(c[2]), "+f"(c[3])
        : "r"(a[0]), "r"(a[1]), "r"(a[2]), "r"(a[3]), "r"(b[0]), "r"(b[1]));
}

__global__ void __launch_bounds__(256, 2) k_gemm_mma() {
    extern __shared__ char dsm[];
    const uint32_t sb = smem_u32(dsm);
    const int tid  = threadIdx.x;
    const int wid  = tid >> 5;
    const int lane = tid & 31;
    const int wm   = wid >> 1;
    const int wn   = wid & 1;
    const int bm   = blockIdx.y * TB_M;          // M slow
    const int n0   = blockIdx.x * TB_N;          // N fast -> X L2 reuse

    const int qr = lane >> 2;
    const int qc = lane & 3;

    const uint32_t a_l = (uint32_t)((wm * 32 + (lane & 15)) * ROWB + ((lane & 16) ? 16 : 0));
    const uint32_t b_l = (uint32_t)((wn * 64 + (lane & 7) + ((lane & 16) ? 8 : 0)) * ROWB
                                    + ((lane & 8) ? 16 : 0));

    const int crow = tid >> 2;                   // cp.async: 0..63 (+64)
    const int cseg = tid & 3;

    float acc[2][8][4];
    #pragma unroll
    for (int mi = 0; mi < 2; mi++)
        #pragma unroll
        for (int ni = 0; ni < 8; ni++)
            #pragma unroll
            for (int j = 0; j < 4; j++) acc[mi][ni][j] = 0.f;

    #define ISSUE(stage, kc) { \
        const int k0_ = (kc) * 32; \
        const uint32_t base_ = sb + (stage) * STAGE_BYTES; \
        _Pragma("unroll") \
        for (int p = 0; p < 2; p++) { \
            int row = crow + p * 64; \
            int gr = bm + row; if (gr > N_NODES - 1) gr = N_NODES - 1; \
            CP16(base_ + OFF_AHI + row * ROWB + cseg * 16, \
                 (const char*)(g_xhi + gr * CH + k0_ + cseg * 8)); \
            CP16(base_ + OFF_ALO + row * ROWB + cseg * 16, \
                 (const char*)(g_xlo + gr * CH + k0_ + cseg * 8)); \
            CP16(base_ + OFF_BHI + row * ROWB + cseg * 16, \
                 (const char*)(g_whi + (n0 + row) * CH + k0_ + cseg * 8)); \
            CP16(base_ + OFF_BLO + row * ROWB + cseg * 16, \
                 (const char*)(g_wlo + (n0 + row) * CH + k0_ + cseg * 8)); \
        } \
        asm volatile("cp.async.commit_group;"); }

    ISSUE(0, 0)

    for (int kc = 0; kc < 8; kc++) {
        const int cur = kc & 1;
        if (kc < 7) {
            ISSUE(cur ^ 1, kc + 1)
            asm volatile("cp.async.wait_group 1;");
        } else {
            asm volatile("cp.async.wait_group 0;");
        }
        __syncthreads();

        const uint32_t base = sb + cur * STAGE_BYTES;
        const uint32_t aHi = base + OFF_AHI + a_l;
        const uint32_t aLo = base + OFF_ALO + a_l;
        const uint32_t bHi = base + OFF_BHI + b_l;
        const uint32_t bLo = base + OFF_BLO + b_l;

        #pragma unroll
        for (int ks = 0; ks < 2; ks++) {
            const uint32_t kb = ks * 32;          // 16 bf16 = 32 bytes
            uint32_t ah[2][4], al[2][4], bh[8][2], bl[8][2];
            #pragma unroll
            for (int mi = 0; mi < 2; mi++) {
                ldsm4(ah[mi], aHi + mi * (16 * ROWB) + kb);
                ldsm4(al[mi], aLo + mi * (16 * ROWB) + kb);
            }
            #pragma unroll
            for (int p = 0; p < 4; p++) {
                ldsm4(&bh[2 * p][0], bHi + p * (16 * ROWB) + kb);
                ldsm4(&bl[2 * p][0], bLo + p * (16 * ROWB) + kb);
            }
            #pragma unroll
            for (int mi = 0; mi < 2; mi++)
                #pragma unroll
                for (int ni = 0; ni < 8; ni++)
                    mma16816(acc[mi][ni], ah[mi], bh[ni]);
            #pragma unroll
            for (int mi = 0; mi < 2; mi++)
                #pragma unroll
                for (int ni = 0; ni < 8; ni++)
                    mma16816(acc[mi][ni], ah[mi], bl[ni]);
            #pragma unroll
            for (int mi = 0; mi < 2; mi++)
                #pragma unroll
                for (int ni = 0; ni < 8; ni++)
                    mma16816(acc[mi][ni], al[mi], bh[ni]);
        }
        __syncthreads();
    }

    // ---- epilogue: fp16 stores (cols 2qc, 2qc+1) ----
    #pragma unroll
    for (int mi = 0; mi < 2; mi++) {
        int r0 = bm + wm * 32 + mi * 16 + qr;
        #pragma unroll
        for (int ni = 0; ni < 8; ni++) {
            int cg = n0 + wn * 64 + ni * 8 + qc * 2;
            if (r0 < N_NODES) {
                __half2 h = __floats2half2_rn(acc[mi][ni][0], acc[mi][ni][1]);
                *(__half2*)&g_xwh[r0 * CH + cg] = h;
            }
            if (r0 + 8 < N_NODES) {
                __half2 h = __floats2half2_rn(acc[mi][ni][2], acc[mi][ni][3]);
                *(__half2*)&g_xwh[(r0 + 8) * CH + cg] = h;
            }
        }
    }
}

// ---------------- fused gather + relu + node-sum (fp16 xw, self edge in CSR) -----
#define GATHER_BLOCKS 1184
__global__ void __launch_bounds__(256) k_gather(const float* __restrict__ conv_b) {
    __shared__ float sacc[CH];
    const int tid  = threadIdx.x;
    const int lane = tid & 31;
    const int warp = (blockIdx.x * blockDim.x + tid) >> 5;
    const int nwarps = (GATHER_BLOCKS * 256) >> 5;
    const int c = lane << 3;

    sacc[tid] = 0.f;
    __syncthreads();

    const float4 b0 = *(const float4*)&conv_b[c];
    const float4 b1 = *(const float4*)&conv_b[c + 4];
    float hs[8] = {0.f,0.f,0.f,0.f,0.f,0.f,0.f,0.f};

    int beg = 0, cnt = 0;
    if (warp < N_NODES) { beg = g_rowptr[warp]; cnt = g_cnt[warp]; }

    for (int n = warp; n < N_NODES; n += nwarps) {
        int nn = n + nwarps, nbeg = 0, ncnt = 0;
        if (nn < N_NODES) { nbeg = g_rowptr[nn]; ncnt = g_cnt[nn]; }

        float a[8] = {0.f,0.f,0.f,0.f,0.f,0.f,0.f,0.f};
        const int2* ec = g_csr + beg;
        const int nb = cnt >> 3;

        #define GSTEP(e) { \
            uint4 v = *(const uint4*)&g_xwh[(e).x * CH + c]; \
            float cf = __int_as_float((e).y); \
            float2 f0 = __half22float2(*(__half2*)&v.x); \
            float2 f1 = __half22float2(*(((__half2*)&v.x) + 1)); \
            float2 f2 = __half22float2(*(__half2*)&v.z); \
            float2 f3 = __half22float2(*(((__half2*)&v.z) + 1)); \
            a[0] += cf * f0.x; a[1] += cf * f0.y; \
            a[2] += cf * f1.x; a[3] += cf * f1.y; \
            a[4] += cf * f2.x; a[5] += cf * f2.y; \
            a[6] += cf * f3.x; a[7] += cf * f3.y; }

        if (nb > 0) {
            int2 m0 = ec[0], m1 = ec[1], m2 = ec[2], m3 = ec[3],
                 m4 = ec[4], m5 = ec[5], m6 = ec[6], m7 = ec[7];
            for (int bi = 0; bi < nb; bi++) {
                int2 c0 = m0, c1 = m1, c2 = m2, c3 = m3,
                     c4 = m4, c5 = m5, c6 = m6, c7 = m7;
                if (bi + 1 < nb) {
                    const int2* nx = ec + (bi + 1) * 8;
                    m0 = nx[0]; m1 = nx[1]; m2 = nx[2]; m3 = nx[3];
                    m4 = nx[4]; m5 = nx[5]; m6 = nx[6]; m7 = nx[7];
                }
                GSTEP(c0) GSTEP(c1) GSTEP(c2) GSTEP(c3)
                GSTEP(c4) GSTEP(c5) GSTEP(c6) GSTEP(c7)
            }
        }
        {   // batched remainder
            int base = nb << 3;
            int rem  = cnt - base;
            int2 rr[7];
            #pragma unroll
            for (int j = 0; j < 7; j++) if (j < rem) rr[j] = ec[base + j];
            #pragma unroll
            for (int j = 0; j < 7; j++) if (j < rem) GSTEP(rr[j])
        }
        #undef GSTEP
        hs[0] += fmaxf(a[0] + b0.x, 0.f);
        hs[1] += fmaxf(a[1] + b0.y, 0.f);
        hs[2] += fmaxf(a[2] + b0.z, 0.f);
        hs[3] += fmaxf(a[3] + b0.w, 0.f);
        hs[4] += fmaxf(a[4] + b1.x, 0.f);
        hs[5] += fmaxf(a[5] + b1.y, 0.f);
        hs[6] += fmaxf(a[6] + b1.z, 0.f);
        hs[7] += fmaxf(a[7] + b1.w, 0.f);

        beg = nbeg; cnt = ncnt;
    }
    #pragma unroll
    for (int i = 0; i < 8; i++) atomicAdd(&sacc[c + i], hs[i]);
    __syncthreads();
    atomicAdd(&g_s[tid], sacc[tid]);
}

// ---------------- 4 tanh GEMVs -----------------------------------------------------
__global__ void k_gemv(const float* __restrict__ fc1w, const float* __restrict__ fc1b,
                       const float* __restrict__ fc2w, const float* __restrict__ fc2b,
                       const float* __restrict__ fc3w, const float* __restrict__ fc3b,
                       const float* __restrict__ fc4w, const float* __restrict__ fc4b,
                       float* __restrict__ out) {
    __shared__ float ss[CH];
    const int t = threadIdx.x;
    if (t < CH) ss[t] = g_s[t];
    __syncthreads();

    const float* w; const float* bb; int row;
    if (t < 256)      { w = fc1w; bb = fc1b; row = t; }
    else if (t < 512) { w = fc2w; bb = fc2b; row = t - 256; }
    else if (t < 640) { w = fc3w; bb = fc3b; row = t - 512; }
    else              { w = fc4w; bb = fc4b; row = t - 640; }

    float acc = bb[row];
    const float4* wr = (const float4*)(w + row * CH);
    #pragma unroll
    for (int k = 0; k < CH / 4; k++) {
        float4 wv = wr[k];
        acc += ss[4 * k + 0] * wv.x + ss[4 * k + 1] * wv.y +
               ss[4 * k + 2] * wv.z + ss[4 * k + 3] * wv.w;
    }
    out[t] = tanhf(acc);
}

// ---------------- launch -------------------------------------------------------------
extern "C" void kernel_launch(void* const* d_in, const int* in_sizes, int n_in,
                              void* d_out, int out_size) {
    const float* x      = (const float*)d_in[0];
    const int*   ei     = (const int*)  d_in[1];
    const float* conv_w = (const float*)d_in[2];
    const float* conv_b = (const float*)d_in[3];
    const float* fc1w   = (const float*)d_in[4];
    const float* fc1b   = (const float*)d_in[5];
    const float* fc2w   = (const float*)d_in[6];
    const float* fc2b   = (const float*)d_in[7];
    const float* fc3w   = (const float*)d_in[8];
    const float* fc3b   = (const float*)d_in[9];
    const float* fc4w   = (const float*)d_in[10];
    const float* fc4b   = (const float*)d_in[11];
    float* out = (float*)d_out;

    const int* src = ei;
    const int* dst = ei + N_EDGES;

    static cudaStream_t sB = 0;
    static cudaEvent_t ePrep = 0, eGemm = 0;
    static bool inited = false;
    if (!inited) {
        cudaFuncSetAttribute(k_gemm_mma, cudaFuncAttributeMaxDynamicSharedMemorySize,
                             GEMM_SMEM);
        cudaStreamCreateWithFlags(&sB, cudaStreamNonBlocking);
        cudaEventCreateWithFlags(&ePrep, cudaEventDisableTiming);
        cudaEventCreateWithFlags(&eGemm, cudaEventDisableTiming);
        inited = true;
    }

    // sB: splitX (needs only X) runs concurrently with prep+count on main
    k_splitX<<<N_NODES * CH / 4 / 256, 256, 0, sB>>>(x);       // 1
    k_prep<<<256, 256>>>(conv_w);                              // 2 (main)
    cudaEventRecord(ePrep, 0);
    k_count<<<(N_EDGES + 255) / 256, 256>>>(src, dst);         // 3 (main)

    // sB: GEMM after splitX (stream order) and prep (event)
    cudaStreamWaitEvent(sB, ePrep, 0);
    dim3 gg(CH / TB_N, (N_NODES + TB_M - 1) / TB_M);
    k_gemm_mma<<<gg, 256, GEMM_SMEM, sB>>>();                  // 4 <- profiled
    cudaEventRecord(eGemm, sB);

    // main: CSR chain (overlaps GEMM)
    k_scan1<<<NSCAN, 256>>>();                                 // 5
    k_scan2<<<1, 256>>>();                                     // 6
    k_scan3d<<<NSCAN, 256>>>();                                // 7
    k_fill<<<(N_EDGES + 255) / 256, 256>>>(src, dst);          // 8

    // join: gather needs CSR (stream order) + GEMM (event)
    cudaStreamWaitEvent(0, eGemm, 0);
    k_gather<<<GATHER_BLOCKS, 256>>>(conv_b);                  // 9
    k_gemv<<<1, 768>>>(fc1w, fc1b, fc2w, fc2b, fc3w, fc3b, fc4w, fc4b, out); // 10
}

// round 14
// speedup vs baseline: 1.3429x; 1.1169x over previous
#include <cuda_runtime.h>
#include <cuda_fp16.h>
#include <cstdint>

#define N_NODES 50000
#define CH      256
#define N_EDGES 800000
#define N_CSR   (N_EDGES + N_NODES)
#define NSCAN   196          // ceil(50000/256)

// ---------------- scratch (device globals) ------------------------------------
__device__ __half g_xwh[N_NODES * CH];   // x @ conv_w, fp16 (25.6 MB, L2-resident)
__device__ __half g_xh [N_NODES * CH];   // X hi fp16
__device__ __half g_xl [N_NODES * CH];   // X lo fp16 (X - hi)
__device__ __half g_whf[CH * CH];        // W^T fp16, [n][k]
__device__ float g_dinv[N_NODES];
__device__ int   g_sdeg[N_NODES];
__device__ int   g_cnt [N_NODES];
__device__ int   g_rowptr[N_NODES];
__device__ int   g_cursor[N_NODES];
__device__ int   g_bsum[NSCAN];
__device__ int2  g_csr[N_CSR];           // {src, coef-as-int}; includes self edges
__device__ float g_s[CH];

// ---------------- prep: init counters + fp16 transpose W ------------------------
__global__ void k_prep(const float* __restrict__ W) {
    int i = blockIdx.x * blockDim.x + threadIdx.x;   // 0..65535
    if (i < N_NODES) { g_sdeg[i] = 1; g_cnt[i] = 1; }  // cnt=1: self edge slot
    if (i < CH)      g_s[i] = 0.0f;
    int k = i >> 8, n = i & 255;
    g_whf[n * CH + k] = __float2half_rn(W[i]);        // W[k][n] -> WT[n][k]
}

// ---------------- X fp16 hi/lo split ---------------------------------------------
__global__ void k_splitX(const float* __restrict__ X) {
    int idx = blockIdx.x * blockDim.x + threadIdx.x;  // 0..3,199,999 (float4)
    float4 v = ((const float4*)X)[idx];
    __half2 h0 = __floats2half2_rn(v.x, v.y);
    __half2 h1 = __floats2half2_rn(v.z, v.w);
    __half2 l0 = __floats2half2_rn(v.x - __half2float(h0.x),
                                   v.y - __half2float(h0.y));
    __half2 l1 = __floats2half2_rn(v.z - __half2float(h1.x),
                                   v.w - __half2float(h1.y));
    uint2 hh, ll;
    hh.x = *(uint32_t*)&h0; hh.y = *(uint32_t*)&h1;
    ll.x = *(uint32_t*)&l0; ll.y = *(uint32_t*)&l1;
    ((uint2*)g_xh)[idx] = hh;
    ((uint2*)g_xl)[idx] = ll;
}

// ---------------- degree histograms ----------------------------------------------
__global__ void k_count(const int* __restrict__ src, const int* __restrict__ dst) {
    int e = blockIdx.x * blockDim.x + threadIdx.x;
    if (e < N_EDGES) {
        atomicAdd(&g_sdeg[src[e]], 1);
        atomicAdd(&g_cnt[dst[e]], 1);
    }
}

// ---------------- 3-kernel exclusive scan over g_cnt ----------------------------
__global__ void k_scan1() {
    __shared__ int sh[256];
    int t = threadIdx.x, i = blockIdx.x * 256 + t;
    int v = (i < N_NODES) ? g_cnt[i] : 0;
    sh[t] = v; __syncthreads();
    #pragma unroll
    for (int off = 1; off < 256; off <<= 1) {
        int add = (t >= off) ? sh[t - off] : 0;
        __syncthreads();
        sh[t] += add;
        __syncthreads();
    }
    if (i < N_NODES) g_rowptr[i] = sh[t] - v;
    if (t == 255) g_bsum[blockIdx.x] = sh[255];
}

__global__ void k_scan2() {
    __shared__ int sh[256];
    int t = threadIdx.x;
    int v = (t < NSCAN) ? g_bsum[t] : 0;
    sh[t] = v; __syncthreads();
    #pragma unroll
    for (int off = 1; off < 256; off <<= 1) {
        int add = (t >= off) ? sh[t - off] : 0;
        __syncthreads();
        sh[t] += add;
        __syncthreads();
    }
    if (t < NSCAN) g_bsum[t] = sh[t] - v;
}

// scan finalize + dinv + write self edge at rowptr[i]
__global__ void k_scan3d() {
    int i = blockIdx.x * blockDim.x + threadIdx.x;
    if (i < N_NODES) {
        int r = g_rowptr[i] + g_bsum[i >> 8];
        g_rowptr[i] = r;
        g_cursor[i] = r + 1;                         // slot r = self edge
        int deg = g_sdeg[i];
        g_dinv[i] = rsqrtf((float)deg);
        g_csr[r] = make_int2(i, __float_as_int(1.0f / (float)deg));
    }
}

// ---------------- CSR fill (packed int2 metadata) --------------------------------
__global__ void k_fill(const int* __restrict__ src, const int* __restrict__ dst) {
    int e = blockIdx.x * blockDim.x + threadIdx.x;
    if (e < N_EDGES) {
        int s = src[e], d = dst[e];
        int pos = atomicAdd(&g_cursor[d], 1);
        float cf = g_dinv[s] * g_dinv[d];
        g_csr[pos] = make_int2(s, __float_as_int(cf));
    }
}

// =================================================================================
// 2-term fp16 GEMM: D = (Xh + Xl) @ Wh   (fp32 accumulate)
// cp.async 2-stage, ldmatrix, 2 CTAs/SM. CTA 128x128, 8 warps 4(M)x2(N), K chunk 32.
// =================================================================================
#define TB_M 128
#define TB_N 128
#define ROWB 80            // bytes per SMEM row (32 fp16 = 64B + pad) -> LDSM ok
#define OFF_AHI 0
#define OFF_ALO 10240
#define OFF_B   20480
#define STAGE_BYTES 30720
#define GEMM_SMEM (2 * STAGE_BYTES)

__device__ __forceinline__ uint32_t smem_u32(const void* p) {
    uint32_t a;
    asm("{ .reg .u64 t; cvta.to.shared.u64 t, %1; cvt.u32.u64 %0, t; }"
        : "=r"(a) : "l"(p));
    return a;
}
#define CP16(dst, src) \
    asm volatile("cp.async.cg.shared.global [%0], [%1], 16;" :: "r"(dst), "l"(src))

__device__ __forceinline__ void ldsm4(uint32_t* r, uint32_t addr) {
    asm volatile("ldmatrix.sync.aligned.m8n8.x4.shared.b16 {%0,%1,%2,%3}, [%4];"
        : "=r"(r[0]), "=r"(r[1]), "=r"(r[2]), "=r"(r[3]) : "r"(addr));
}

__device__ __forceinline__ void mma_f16(float* c, const uint32_t* a, const uint32_t* b) {
    asm volatile(
        "mma.sync.aligned.m16n8k16.row.col.f32.f16.f16.f32 "
        "{%0,%1,%2,%3}, {%4,%5,%6,%7}, {%8,%9}, {%0,%1,%2,%3};"
        : "+f"(c[0]), "+f"(c[1]), "+f"(c[2]), "+f"(c[3])
        : "r"(a[0]), "r"(a[1]), "r"(a[2]), "r"(a[3]), "r"(b[0]), "r"(b[1]));
}

__global__ void __launch_bounds__(256, 2) k_gemm_mma() {
    extern __shared__ char dsm[];
    const uint32_t sb = smem_u32(dsm);
    const int tid  = threadIdx.x;
    const int wid  = tid >> 5;
    const int lane = tid & 31;
    const int wm   = wid >> 1;
    const int wn   = wid & 1;
    const int bm   = blockIdx.y * TB_M;          // M slow
    const int n0   = blockIdx.x * TB_N;          // N fast -> X L2 reuse

    const int qr = lane >> 2;
    const int qc = lane & 3;

    const uint32_t a_l = (uint32_t)((wm * 32 + (lane & 15)) * ROWB + ((lane & 16) ? 16 : 0));
    const uint32_t b_l = (uint32_t)((wn * 64 + (lane & 7) + ((lane & 16) ? 8 : 0)) * ROWB
                                    + ((lane & 8) ? 16 : 0));

    const int crow = tid >> 2;                   // cp.async: 0..63 (+64)
    const int cseg = tid & 3;

    float acc[2][8][4];
    #pragma unroll
    for (int mi = 0; mi < 2; mi++)
        #pragma unroll
        for (int ni = 0; ni < 8; ni++)
            #pragma unroll
            for (int j = 0; j < 4; j++) acc[mi][ni][j] = 0.f;

    #define ISSUE(stage, kc) { \
        const int k0_ = (kc) * 32; \
        const uint32_t base_ = sb + (stage) * STAGE_BYTES; \
        _Pragma("unroll") \
        for (int p = 0; p < 2; p++) { \
            int row = crow + p * 64; \
            int gr = bm + row; if (gr > N_NODES - 1) gr = N_NODES - 1; \
            CP16(base_ + OFF_AHI + row * ROWB + cseg * 16, \
                 (const char*)(g_xh + gr * CH + k0_ + cseg * 8)); \
            CP16(base_ + OFF_ALO + row * ROWB + cseg * 16, \
                 (const char*)(g_xl + gr * CH + k0_ + cseg * 8)); \
            CP16(base_ + OFF_B + row * ROWB + cseg * 16, \
                 (const char*)(g_whf + (n0 + row) * CH + k0_ + cseg * 8)); \
        } \
        asm volatile("cp.async.commit_group;"); }

    ISSUE(0, 0)

    for (int kc = 0; kc < 8; kc++) {
        const int cur = kc & 1;
        if (kc < 7) {
            ISSUE(cur ^ 1, kc + 1)
            asm volatile("cp.async.wait_group 1;");
        } else {
            asm volatile("cp.async.wait_group 0;");
        }
        __syncthreads();

        const uint32_t base = sb + cur * STAGE_BYTES;
        const uint32_t aHi = base + OFF_AHI + a_l;
        const uint32_t aLo = base + OFF_ALO + a_l;
        const uint32_t bB  = base + OFF_B + b_l;

        #pragma unroll
        for (int ks = 0; ks < 2; ks++) {
            const uint32_t kb = ks * 32;          // 16 fp16 = 32 bytes
            uint32_t ah[2][4], al[2][4], bh[8][2];
            #pragma unroll
            for (int mi = 0; mi < 2; mi++) {
                ldsm4(ah[mi], aHi + mi * (16 * ROWB) + kb);
                ldsm4(al[mi], aLo + mi * (16 * ROWB) + kb);
            }
            #pragma unroll
            for (int p = 0; p < 4; p++)
                ldsm4(&bh[2 * p][0], bB + p * (16 * ROWB) + kb);
            #pragma unroll
            for (int mi = 0; mi < 2; mi++)
                #pragma unroll
                for (int ni = 0; ni < 8; ni++)
                    mma_f16(acc[mi][ni], ah[mi], bh[ni]);
            #pragma unroll
            for (int mi = 0; mi < 2; mi++)
                #pragma unroll
                for (int ni = 0; ni < 8; ni++)
                    mma_f16(acc[mi][ni], al[mi], bh[ni]);
        }
        __syncthreads();
    }

    // ---- epilogue: fp16 stores (cols 2qc, 2qc+1) ----
    #pragma unroll
    for (int mi = 0; mi < 2; mi++) {
        int r0 = bm + wm * 32 + mi * 16 + qr;
        #pragma unroll
        for (int ni = 0; ni < 8; ni++) {
            int cg = n0 + wn * 64 + ni * 8 + qc * 2;
            if (r0 < N_NODES) {
                __half2 h = __floats2half2_rn(acc[mi][ni][0], acc[mi][ni][1]);
                *(__half2*)&g_xwh[r0 * CH + cg] = h;
            }
            if (r0 + 8 < N_NODES) {
                __half2 h = __floats2half2_rn(acc[mi][ni][2], acc[mi][ni][3]);
                *(__half2*)&g_xwh[(r0 + 8) * CH + cg] = h;
            }
        }
    }
}

// ---------------- fused gather + relu + node-sum (fp16 xw, self edge in CSR) -----
// First metadata batch of each node is loaded during the PREVIOUS node's gathers.
#define GATHER_BLOCKS 1184
__global__ void __launch_bounds__(256) k_gather(const float* __restrict__ conv_b) {
    __shared__ float sacc[CH];
    const int tid  = threadIdx.x;
    const int lane = tid & 31;
    const int warp = (blockIdx.x * blockDim.x + tid) >> 5;
    const int nwarps = (GATHER_BLOCKS * 256) >> 5;
    const int c = lane << 3;

    sacc[tid] = 0.f;
    __syncthreads();

    const float4 b0 = *(const float4*)&conv_b[c];
    const float4 b1 = *(const float4*)&conv_b[c + 4];
    float hs[8] = {0.f,0.f,0.f,0.f,0.f,0.f,0.f,0.f};

    int beg = 0, cnt = 0;
    int2 fb[8];
    if (warp < N_NODES) {
        beg = g_rowptr[warp]; cnt = g_cnt[warp];
        #pragma unroll
        for (int j = 0; j < 8; j++) if (j < cnt) fb[j] = g_csr[beg + j];
    }

    for (int n = warp; n < N_NODES; n += nwarps) {
        int nn = n + nwarps, nbeg = 0, ncnt = 0;
        if (nn < N_NODES) { nbeg = g_rowptr[nn]; ncnt = g_cnt[nn]; }

        float a[8] = {0.f,0.f,0.f,0.f,0.f,0.f,0.f,0.f};
        const int2* ec = g_csr + beg;
        const int nb = cnt >> 3;

        #define GSTEP(e) { \
            uint4 v = *(const uint4*)&g_xwh[(e).x * CH + c]; \
            float cf = __int_as_float((e).y); \
            float2 f0 = __half22float2(*(__half2*)&v.x); \
            float2 f1 = __half22float2(*(((__half2*)&v.x) + 1)); \
            float2 f2 = __half22float2(*(__half2*)&v.z); \
            float2 f3 = __half22float2(*(((__half2*)&v.z) + 1)); \
            a[0] += cf * f0.x; a[1] += cf * f0.y; \
            a[2] += cf * f1.x; a[3] += cf * f1.y; \
            a[4] += cf * f2.x; a[5] += cf * f2.y; \
            a[6] += cf * f3.x; a[7] += cf * f3.y; }

        if (nb > 0) {
            int2 m0 = fb[0], m1 = fb[1], m2 = fb[2], m3 = fb[3],
                 m4 = fb[4], m5 = fb[5], m6 = fb[6], m7 = fb[7];
            for (int bi = 0; bi < nb; bi++) {
                int2 c0 = m0, c1 = m1, c2 = m2, c3 = m3,
                     c4 = m4, c5 = m5, c6 = m6, c7 = m7;
                if (bi + 1 < nb) {
                    const int2* nx = ec + (bi + 1) * 8;
                    m0 = nx[0]; m1 = nx[1]; m2 = nx[2]; m3 = nx[3];
                    m4 = nx[4]; m5 = nx[5]; m6 = nx[6]; m7 = nx[7];
                }
                GSTEP(c0) GSTEP(c1) GSTEP(c2) GSTEP(c3)
                GSTEP(c4) GSTEP(c5) GSTEP(c6) GSTEP(c7)
            }
        }
        // prefetch next node's first batch (overlaps remainder work below)
        int2 nfb[8];
        if (nn < N_NODES) {
            #pragma unroll
            for (int j = 0; j < 8; j++) if (j < ncnt) nfb[j] = g_csr[nbeg + j];
        }
        // remainder: if nb==0, the entries are already in fb
        {
            int base = nb << 3;
            int rem  = cnt - base;
            int2 rr[7];
            if (nb == 0) {
                #pragma unroll
                for (int j = 0; j < 7; j++) if (j < rem) rr[j] = fb[j];
            } else {
                #pragma unroll
                for (int j = 0; j < 7; j++) if (j < rem) rr[j] = ec[base + j];
            }
            #pragma unroll
            for (int j = 0; j < 7; j++) if (j < rem) GSTEP(rr[j])
        }
        #undef GSTEP
        hs[0] += fmaxf(a[0] + b0.x, 0.f);
        hs[1] += fmaxf(a[1] + b0.y, 0.f);
        hs[2] += fmaxf(a[2] + b0.z, 0.f);
        hs[3] += fmaxf(a[3] + b0.w, 0.f);
        hs[4] += fmaxf(a[4] + b1.x, 0.f);
        hs[5] += fmaxf(a[5] + b1.y, 0.f);
        hs[6] += fmaxf(a[6] + b1.z, 0.f);
        hs[7] += fmaxf(a[7] + b1.w, 0.f);

        beg = nbeg; cnt = ncnt;
        #pragma unroll
        for (int j = 0; j < 8; j++) fb[j] = nfb[j];
    }
    #pragma unroll
    for (int i = 0; i < 8; i++) atomicAdd(&sacc[c + i], hs[i]);
    __syncthreads();
    atomicAdd(&g_s[tid], sacc[tid]);
}

// ---------------- 4 tanh GEMVs -----------------------------------------------------
__global__ void k_gemv(const float* __restrict__ fc1w, const float* __restrict__ fc1b,
                       const float* __restrict__ fc2w, const float* __restrict__ fc2b,
                       const float* __restrict__ fc3w, const float* __restrict__ fc3b,
                       const float* __restrict__ fc4w, const float* __restrict__ fc4b,
                       float* __restrict__ out) {
    __shared__ float ss[CH];
    const int t = threadIdx.x;
    if (t < CH) ss[t] = g_s[t];
    __syncthreads();

    const float* w; const float* bb; int row;
    if (t < 256)      { w = fc1w; bb = fc1b; row = t; }
    else if (t < 512) { w = fc2w; bb = fc2b; row = t - 256; }
    else if (t < 640) { w = fc3w; bb = fc3b; row = t - 512; }
    else              { w = fc4w; bb = fc4b; row = t - 640; }

    float acc = bb[row];
    const float4* wr = (const float4*)(w + row * CH);
    #pragma unroll
    for (int k = 0; k < CH / 4; k++) {
        float4 wv = wr[k];
        acc += ss[4 * k + 0] * wv.x + ss[4 * k + 1] * wv.y +
               ss[4 * k + 2] * wv.z + ss[4 * k + 3] * wv.w;
    }
    out[t] = tanhf(acc);
}

// ---------------- launch -------------------------------------------------------------
extern "C" void kernel_launch(void* const* d_in, const int* in_sizes, int n_in,
                              void* d_out, int out_size) {
    const float* x      = (const float*)d_in[0];
    const int*   ei     = (const int*)  d_in[1];
    const float* conv_w = (const float*)d_in[2];
    const float* conv_b = (const float*)d_in[3];
    const float* fc1w   = (const float*)d_in[4];
    const float* fc1b   = (const float*)d_in[5];
    const float* fc2w   = (const float*)d_in[6];
    const float* fc2b   = (const float*)d_in[7];
    const float* fc3w   = (const float*)d_in[8];
    const float* fc3b   = (const float*)d_in[9];
    const float* fc4w   = (const float*)d_in[10];
    const float* fc4b   = (const float*)d_in[11];
    float* out = (float*)d_out;

    const int* src = ei;
    const int* dst = ei + N_EDGES;

    static cudaStream_t sB = 0;
    static cudaEvent_t ePrep = 0, eGemm = 0;
    static bool inited = false;
    if (!inited) {
        cudaFuncSetAttribute(k_gemm_mma, cudaFuncAttributeMaxDynamicSharedMemorySize,
                             GEMM_SMEM);
        cudaStreamCreateWithFlags(&sB, cudaStreamNonBlocking);
        cudaEventCreateWithFlags(&ePrep, cudaEventDisableTiming);
        cudaEventCreateWithFlags(&eGemm, cudaEventDisableTiming);
        inited = true;
    }

    // sB: splitX (needs only X) runs concurrently with prep+count on main
    k_splitX<<<N_NODES * CH / 4 / 256, 256, 0, sB>>>(x);       // 1
    k_prep<<<256, 256>>>(conv_w);                              // 2 (main)
    cudaEventRecord(ePrep, 0);
    k_count<<<(N_EDGES + 255) / 256, 256>>>(src, dst);         // 3 (main)

    // sB: GEMM after splitX (stream order) and prep (event)
    cudaStreamWaitEvent(sB, ePrep, 0);
    dim3 gg(CH / TB_N, (N_NODES + TB_M - 1) / TB_M);
    k_gemm_mma<<<gg, 256, GEMM_SMEM, sB>>>();                  // 4 <- profiled
    cudaEventRecord(eGemm, sB);

    // main: CSR chain (overlaps GEMM)
    k_scan1<<<NSCAN, 256>>>();                                 // 5
    k_scan2<<<1, 256>>>();                                     // 6
    k_scan3d<<<NSCAN, 256>>>();                                // 7
    k_fill<<<(N_EDGES + 255) / 256, 256>>>(src, dst);          // 8

    // join: gather needs CSR (stream order) + GEMM (event)
    cudaStreamWaitEvent(0, eGemm, 0);
    k_gather<<<GATHER_BLOCKS, 256>>>(conv_b);                  // 9
    k_gemv<<<1, 768>>>(fc1w, fc1b, fc2w, fc2b, fc3w, fc3b, fc4w, fc4b, out); // 10
}